// round 12
// baseline (speedup 1.0000x reference)
#include <cuda_runtime.h>
#include <cstdint>
#include <cstddef>

// Problem constants
#define L_S_C   4096
#define QSTART  2048
#define L_NS_C  64
#define LQ      2112
#define LK      4160
#define DM      1024
#define NH      16
#define DH      64

// Scratch (device globals). g_Q padded +64 rows for the clamped last q-block.
__device__ float g_Q[(size_t)(LQ + 64) * DM];
__device__ float g_V[(size_t)LK * DM];
__device__ float g_AO[(size_t)LQ * DM];          // k-permuted layout
__device__ float g_xr[(size_t)LK * DM];          // rounded x (row-major [m][k]), k-permuted
__device__ float g_Wsr[(size_t)(3 * DM) * DM];   // rounded W_S^T [n][k], k-permuted
__device__ float g_Wor[(size_t)DM * DM];         // rounded W_out^T [n][k], k-permuted
__device__ float g_Kp[(size_t)LK * DM];          // K, head-dim 8-block permuted
__device__ float g_Vt[(size_t)DM * LK];          // V^T [d][token], token 8-block permuted

// 8-block permutation: stored position p holds orig col sigma(p):
// sigma(2t)=t, sigma(2t+1)=t+4  -> stored order [0,4,1,5,2,6,3,7].
// Inverse: pos(c) = c<4 ? 2c : 2c-7.

__device__ __forceinline__ uint32_t f2tf(float x) {
    uint32_t r;
    asm("cvt.rna.tf32.f32 %0, %1;" : "=r"(r) : "f"(x));
    return r;
}
__device__ __forceinline__ float rnd(float x) { return __uint_as_float(f2tf(x)); }
__device__ __forceinline__ uint32_t fu(float x) { return __float_as_uint(x); }

__device__ __forceinline__ void mma8(float* c, const uint32_t* a, const uint32_t* b) {
    asm volatile(
        "mma.sync.aligned.m16n8k8.row.col.f32.tf32.tf32.f32 "
        "{%0,%1,%2,%3}, {%4,%5,%6,%7}, {%8,%9}, {%0,%1,%2,%3};\n"
        : "+f"(c[0]), "+f"(c[1]), "+f"(c[2]), "+f"(c[3])
        : "r"(a[0]), "r"(a[1]), "r"(a[2]), "r"(a[3]), "r"(b[0]), "r"(b[1]));
}

__device__ __forceinline__ void cp16(void* dst, const void* src, int sz) {
    uint32_t d = (uint32_t)__cvta_generic_to_shared(dst);
    asm volatile("cp.async.cg.shared.global [%0], [%1], 16, %2;\n"
                 :: "r"(d), "l"(src), "r"(sz));
}
#define CP_COMMIT()  asm volatile("cp.async.commit_group;\n")
#define CP_WAIT(n)   asm volatile("cp.async.wait_group %0;\n" :: "n"(n))

// ============================================================================
// Prep: round+permute x; transpose+round+permute W_S / W_out.
// ============================================================================
__global__ void __launch_bounds__(256)
prep_x(const float* __restrict__ x) {
    const int NT8 = (int)((size_t)LK * DM / 8);
    for (int i = blockIdx.x * blockDim.x + threadIdx.x; i < NT8;
         i += gridDim.x * blockDim.x) {
        const float4* s = (const float4*)x + 2 * i;
        float4 v0 = s[0], v1 = s[1];
        float4 w0 = make_float4(rnd(v0.x), rnd(v1.x), rnd(v0.y), rnd(v1.y));
        float4 w1 = make_float4(rnd(v0.z), rnd(v1.z), rnd(v0.w), rnd(v1.w));
        ((float4*)g_xr)[2 * i]     = w0;
        ((float4*)g_xr)[2 * i + 1] = w1;
    }
}

__global__ void __launch_bounds__(256)
prep_tr(const float* __restrict__ src, int which) {
    __shared__ float t[32][33];
    const int C = which ? DM : 3 * DM;
    float* dst = which ? g_Wor : g_Wsr;
    const int c0 = blockIdx.x * 32, r0 = blockIdx.y * 32;
    const int tx = threadIdx.x & 31, ty = threadIdx.x >> 5;
#pragma unroll
    for (int i = 0; i < 4; i++)
        t[ty + i * 8][tx] = rnd(src[(size_t)(r0 + ty + i * 8) * C + c0 + tx]);
    __syncthreads();
    const int tx8 = tx & 7;
    const int pk = (tx & ~7) + (tx8 < 4 ? 2 * tx8 : 2 * tx8 - 7);
#pragma unroll
    for (int i = 0; i < 4; i++)
        dst[(size_t)(c0 + ty + i * 8) * DM + r0 + pk] = t[tx][ty + i * 8];
}

// V transpose repack: [d][token], token 8-block permuted.
__global__ void __launch_bounds__(256)
repack_Vt() {
    __shared__ float t[32][33];
    const int tok0 = blockIdx.x * 32, d0 = blockIdx.y * 32;
    const int tx = threadIdx.x & 31, ty = threadIdx.x >> 5;
#pragma unroll
    for (int i = 0; i < 4; i++)
        t[ty + i * 8][tx] = g_V[(size_t)(tok0 + ty + i * 8) * DM + d0 + tx];
    __syncthreads();
    const int tx8 = tx & 7;
    const int ptok = (tx & ~7) + (tx8 < 4 ? 2 * tx8 : 2 * tx8 - 7);
#pragma unroll
    for (int i = 0; i < 4; i++)
        g_Vt[(size_t)(d0 + ty + i * 8) * LK + tok0 + ptok] = t[tx][ty + i * 8];
}

// Zero d_out for atomic-accumulating split-K output projection.
__global__ void __launch_bounds__(256)
zeroC(float* __restrict__ C) {
    int i = blockIdx.x * blockDim.x + threadIdx.x;
    if (i < LQ * DM / 4) ((float4*)C)[i] = make_float4(0.f, 0.f, 0.f, 0.f);
}

// ============================================================================
// tf32 warp-MMA GEMM tile v3: 4-stage cp.async pipeline, k-chunk 16,
// prefetch distance 3, ONE barrier per k-iter. Stage s: A @ s*6144,
// B @ s*6144+3072 (floats, stride 24). Smem total 4*6144*4 = 96 KB.
// MODE 0: scatter rnd() into g_Q/g_Kp(permuted)/g_V. MODE 1: atomicAdd into C.
// ============================================================================
template <int MODE>
__device__ __forceinline__ void gemm_tile(const float* __restrict__ A,
                                          const float* __restrict__ Bt,
                                          float* __restrict__ C,
                                          int M, int N, int Ks, int kBeg, int kLen,
                                          int mBase, int nBase, float* sm) {
    const int tid  = threadIdx.x;
    const int warp = tid >> 5, lane = tid & 31;
    const int gid  = lane >> 2, tig = lane & 3;
    const int wm = (warp >> 2) * 64;
    const int wn = (warp & 3) * 32;

    float c[4][4][4];
#pragma unroll
    for (int i = 0; i < 4; i++)
#pragma unroll
        for (int j = 0; j < 4; j++)
#pragma unroll
            for (int e = 0; e < 4; e++) c[i][j][e] = 0.f;

    // Stage fill: A/B tiles 128 rows x 16 k-floats; 2 x cp16 per thread per matrix.
    auto issue = [&](int k0, int s) {
        float* As = sm + s * 6144;
        float* Bs = As + 3072;
#pragma unroll
        for (int i = 0; i < 2; i++) {
            int ch  = i * 256 + tid;          // 0..511
            int row = ch >> 2;
            int cc  = (ch & 3) << 2;
            int grow = mBase + row;
            int ok = (MODE == 1) ? (grow < M) : 1;
            cp16(&As[row * 24 + cc], A + (size_t)(ok ? grow : 0) * Ks + k0 + cc,
                 ok ? 16 : 0);
            cp16(&Bs[row * 24 + cc], Bt + (size_t)(nBase + row) * Ks + k0 + cc, 16);
        }
        CP_COMMIT();
    };

    issue(kBeg, 0);
    issue(kBeg + 16, 1);
    issue(kBeg + 32, 2);

    const int T = kLen / 16;
    for (int t = 0; t < T; t++) {
        CP_WAIT(2);               // oldest (stage t) complete
        __syncthreads();          // all warps done with stage (t-1); data visible
        if (t + 3 < T) issue(kBeg + (t + 3) * 16, (t + 3) & 3);
        else CP_COMMIT();         // empty group keeps FIFO arithmetic aligned

        float* As = sm + (t & 3) * 6144;
        float* Bs = As + 3072;

#pragma unroll
        for (int ks = 0; ks < 2; ks++) {
            const int kcol = ks * 8 + 2 * tig;   // stored pos pair -> cols (k, k+4)
            uint32_t a[4][4];
#pragma unroll
            for (int mt = 0; mt < 4; mt++) {
                int r = wm + mt * 16 + gid;
                float2 u = *(const float2*)&As[r * 24 + kcol];
                float2 w = *(const float2*)&As[(r + 8) * 24 + kcol];
                a[mt][0] = fu(u.x); a[mt][2] = fu(u.y);
                a[mt][1] = fu(w.x); a[mt][3] = fu(w.y);
            }
            uint32_t b[4][2];
#pragma unroll
            for (int nt = 0; nt < 4; nt++) {
                int rn = wn + nt * 8 + gid;
                float2 v = *(const float2*)&Bs[rn * 24 + kcol];
                b[nt][0] = fu(v.x); b[nt][1] = fu(v.y);
            }
#pragma unroll
            for (int mt = 0; mt < 4; mt++)
#pragma unroll
                for (int nt = 0; nt < 4; nt++)
                    mma8(c[mt][nt], a[mt], b[nt]);
        }
    }

#pragma unroll
    for (int mt = 0; mt < 4; mt++) {
#pragma unroll
        for (int nt = 0; nt < 4; nt++) {
#pragma unroll
            for (int e = 0; e < 4; e++) {
                int row = mBase + wm + mt * 16 + gid + ((e >> 1) << 3);
                int col = nBase + wn + nt * 8 + 2 * tig + (e & 1);
                float v = c[mt][nt][e];
                if (MODE == 0) {
                    v = rnd(v);
                    if (col < DM) {
                        if (row >= QSTART) g_Q[(size_t)(row - QSTART) * DM + col] = v;
                    } else if (col < 2 * DM) {
                        int ck = col - DM;
                        int c8 = ck & 7;
                        int p8 = (c8 < 4) ? 2 * c8 : 2 * c8 - 7;
                        g_Kp[(size_t)row * DM + (ck & ~7) + p8] = v;
                    } else {
                        g_V[(size_t)row * DM + (col - 2 * DM)] = v;
                    }
                } else {
                    if (row < M) atomicAdd(&C[(size_t)row * N + col], v);
                }
            }
        }
    }
}

// ============================================================================
// Fused qkv: 640 live GEMM tiles + 192 NS streaming blocks (10:3 interleave).
// ============================================================================
__global__ void __launch_bounds__(256, 2)
fused_qkv(const float* __restrict__ x, const float* __restrict__ W_NS) {
    extern __shared__ float sm[];
    const int bid = blockIdx.x;
    const int grp = bid / 13, rem = bid % 13;
    if (rem < 10) {
        const int g = grp * 10 + rem;       // 0..639
        int mt, nt;
        if (g < 384) { mt = 16 + g / 24; nt = g % 24; }            // rows>=2048: QKV
        else { int g2 = g - 384; mt = g2 / 16; nt = 8 + g2 % 16; } // rows<2048: KV only
        gemm_tile<0>((const float*)g_xr, (const float*)g_Wsr, nullptr,
                     4096, 3072, 1024, 0, 1024, mt * 128, nt * 128, sm);
    } else {
        const int ns  = grp * 3 + (rem - 10);   // 0..191
        const int tok = ns / 3;
        const int cb  = ns % 3;                 // 0=Q, 1=K, 2=V
        const int c4  = cb * 1024 + threadIdx.x * 4;

        const float* xr = x + (size_t)(L_S_C + tok) * DM;
        for (int i = threadIdx.x; i < DM; i += 256) sm[i] = xr[i];
        __syncthreads();

        const float* Wp = W_NS + (size_t)tok * DM * 3072 + c4;
        float4 acc = make_float4(0.f, 0.f, 0.f, 0.f);
#pragma unroll 8
        for (int d = 0; d < DM; d++) {
            float4 w = __ldcs((const float4*)(Wp + (size_t)d * 3072));
            float xv = sm[d];
            acc.x = fmaf(xv, w.x, acc.x);
            acc.y = fmaf(xv, w.y, acc.y);
            acc.z = fmaf(xv, w.z, acc.z);
            acc.w = fmaf(xv, w.w, acc.w);
        }
        float vals[4] = {rnd(acc.x), rnd(acc.y), rnd(acc.z), rnd(acc.w)};

        if (cb == 0) {
            *(float4*)(g_Q + (size_t)(QSTART + tok) * DM + c4) =
                make_float4(vals[0], vals[1], vals[2], vals[3]);
        } else if (cb == 1) {
            int ck = c4 - 1024;
            int b8 = ck & ~7, o0 = ck & 7;       // o0 in {0,4}
#pragma unroll
            for (int j = 0; j < 4; j++) {
                int c8 = o0 + j;
                int p8 = (c8 < 4) ? 2 * c8 : 2 * c8 - 7;
                g_Kp[(size_t)(L_S_C + tok) * DM + b8 + p8] = vals[j];
            }
        } else {
            *(float4*)(g_V + (size_t)(L_S_C + tok) * DM + (c4 - 2048)) =
                make_float4(vals[0], vals[1], vals[2], vals[3]);
        }
    }
}

// Output projection, split-K x2 (blockIdx.z = half), atomicAdd epilogue.
__global__ void __launch_bounds__(256, 2)
gemm_out(float* __restrict__ C) {
    extern __shared__ float sm[];
    gemm_tile<1>((const float*)g_AO, (const float*)g_Wor, C, LQ, 1024, 1024,
                 blockIdx.z * 512, 512, blockIdx.y * 128, blockIdx.x * 128, sm);
}

// ============================================================================
// Flash attention v6: deferred-PV pipeline + l accumulated by an extra
// ones-column MMA (removes the sum shfl-reduction from the critical path).
// 128 q-rows/CTA, 256 thr / 8 warps, Q frags in regs, permuted K / V^T.
// ============================================================================
__global__ void __launch_bounds__(256, 2)
attn_kernel() {
    extern __shared__ float sm[];
    float* Ps  = sm;              // [128][72] (Q staging, then P)
    float* KsA = sm + 9216;       // [64][72]
    float* KsB = sm + 13824;
    float* VsA = sm + 18432;
    float* VsB = sm + 23040;

    const int qtp = 16 - ((int)blockIdx.x >> 4);   // descending work size
    const int h   = blockIdx.x & 15;
    const int qb  = qtp * 128;
    const int tid  = threadIdx.x;
    const int warp = tid >> 5, lane = tid & 31;
    const int gid  = lane >> 2, tig = lane & 3;
    const int rq0  = warp * 16 + gid;

    auto loadKV = [&](int kt, float* Kd, float* Vd) {
        const float* kp = g_Kp + (size_t)kt * 64 * DM + h * DH;
        const float* vp = g_Vt + (size_t)h * DH * LK + kt * 64;
#pragma unroll
        for (int i = 0; i < 4; i++) {
            int idx = tid + i * 256;
            int r = idx >> 4, c4 = (idx & 15) << 2;
            cp16(&Kd[r * 72 + c4], kp + (size_t)r * DM + c4, 16);
            cp16(&Vd[r * 72 + c4], vp + (size_t)r * LK + c4, 16);
        }
        CP_COMMIT();
    };

    loadKV(0, KsA, VsA);

    // Stage Q (unpermuted) into Ps, extract register fragments (warp-own rows).
    for (int i = tid; i < 128 * 16; i += 256) {
        int r = i >> 4, c4 = (i & 15) << 2;
        *(float4*)&Ps[r * 72 + c4] =
            *(const float4*)(g_Q + (size_t)(qb + r) * DM + h * DH + c4);
    }
    __syncthreads();
    uint32_t qa[8][4];
#pragma unroll
    for (int ks = 0; ks < 8; ks++) {
        qa[ks][0] = fu(Ps[rq0 * 72 + ks * 8 + tig] * 0.125f);
        qa[ks][2] = fu(Ps[rq0 * 72 + ks * 8 + tig + 4] * 0.125f);
        qa[ks][1] = fu(Ps[(rq0 + 8) * 72 + ks * 8 + tig] * 0.125f);
        qa[ks][3] = fu(Ps[(rq0 + 8) * 72 + ks * 8 + tig + 4] * 0.125f);
    }

    const int p0 = (tig < 2) ? 4 * tig     : 4 * tig - 7;   // pos of col 2tig
    const int p1 = (tig < 2) ? 4 * tig + 2 : 4 * tig - 5;   // pos of col 2tig+1

    float m0 = -1e30f, m1 = -1e30f;
    float sc0s = 0.f, sc1s = 0.f;   // saved scales for deferred O-rescale
    float o[8][4];
    float ol[4] = {0.f, 0.f, 0.f, 0.f};   // l accumulated via ones-column MMA
    const uint32_t oneb[2] = {0x3f800000u, 0x3f800000u};
#pragma unroll
    for (int i = 0; i < 8; i++)
#pragma unroll
        for (int e = 0; e < 4; e++) o[i][e] = 0.f;

    const int nktFull = 34 + 2 * qtp;
    const int nkt = nktFull < 65 ? nktFull : 65;
    for (int kt = 0; kt < nkt; kt++) {
        CP_WAIT(0);
        __syncthreads();          // K(kt),V(kt) ready & visible

        float* Ks = (kt & 1) ? KsB : KsA;

        // ---- S(kt) = Q @ K^T ----
        float s[8][4];
#pragma unroll
        for (int i = 0; i < 8; i++)
#pragma unroll
            for (int e = 0; e < 4; e++) s[i][e] = 0.f;

#pragma unroll
        for (int ks = 0; ks < 8; ks++) {
            const int kcol = ks * 8 + 2 * tig;
#pragma unroll
            for (int nt = 0; nt < 8; nt++) {
                float2 bv = *(const float2*)&Ks[(nt * 8 + gid) * 72 + kcol];
                uint32_t bb[2] = {fu(bv.x), fu(bv.y)};
                mma8(s[nt], qa[ks], bb);
            }
        }

        // ---- deferred PV(kt-1): O = O*sc + P(kt-1) @ V(kt-1); l likewise ----
        if (kt > 0) {
            float* Vp = (kt & 1) ? VsA : VsB;   // buffer (kt-1)%2
#pragma unroll
            for (int dt = 0; dt < 8; dt++) {
                o[dt][0] *= sc0s; o[dt][1] *= sc0s;
                o[dt][2] *= sc1s; o[dt][3] *= sc1s;
            }
            ol[0] *= sc0s; ol[1] *= sc0s; ol[2] *= sc1s; ol[3] *= sc1s;
#pragma unroll
            for (int ks = 0; ks < 8; ks++) {
                const int kcol = ks * 8 + 2 * tig;
                float2 u = *(const float2*)&Ps[rq0 * 72 + kcol];
                float2 w = *(const float2*)&Ps[(rq0 + 8) * 72 + kcol];
                uint32_t a[4] = {fu(u.x), fu(w.x), fu(u.y), fu(w.y)};
#pragma unroll
                for (int dt = 0; dt < 8; dt++) {
                    float2 bv = *(const float2*)&Vp[(dt * 8 + gid) * 72 + kcol];
                    uint32_t bb[2] = {fu(bv.x), fu(bv.y)};
                    mma8(o[dt], a, bb);
                }
                mma8(ol, a, oneb);   // row-sum of P -> l
            }
        }

        __syncthreads();          // all warps done reading K(kt), V(kt-1), P(kt-1)
        if (kt + 1 < nkt)
            loadKV(kt + 1, (kt & 1) ? KsA : KsB, (kt & 1) ? VsA : VsB);

        // ---- causal mask on last two k-tiles ----
        if (kt >= nkt - 2) {
            const int off = kt * 64 - QSTART - qb;
#pragma unroll
            for (int nt = 0; nt < 8; nt++) {
#pragma unroll
                for (int e = 0; e < 4; e++) {
                    int kc  = nt * 8 + 2 * tig + (e & 1);
                    int rit = warp * 16 + gid + ((e >> 1) << 3);
                    if (kc + off > rit) s[nt][e] = -1e30f;
                }
            }
        }

        // ---- online softmax(kt) -> P(kt), saved scales (no sum reduction) ----
        float rm0 = -1e30f, rm1 = -1e30f;
#pragma unroll
        for (int nt = 0; nt < 8; nt++) {
            rm0 = fmaxf(rm0, fmaxf(s[nt][0], s[nt][1]));
            rm1 = fmaxf(rm1, fmaxf(s[nt][2], s[nt][3]));
        }
        rm0 = fmaxf(rm0, __shfl_xor_sync(0xffffffffu, rm0, 1));
        rm0 = fmaxf(rm0, __shfl_xor_sync(0xffffffffu, rm0, 2));
        rm1 = fmaxf(rm1, __shfl_xor_sync(0xffffffffu, rm1, 1));
        rm1 = fmaxf(rm1, __shfl_xor_sync(0xffffffffu, rm1, 2));

        float mn0 = fmaxf(m0, rm0), mn1 = fmaxf(m1, rm1);
        sc0s = __expf(m0 - mn0);
        sc1s = __expf(m1 - mn1);
        m0 = mn0; m1 = mn1;

        // P(kt) -> Ps at permuted positions (warp-private rows), rounded tf32
#pragma unroll
        for (int nt = 0; nt < 8; nt++) {
            Ps[rq0 * 72 + nt * 8 + p0]       = rnd(__expf(s[nt][0] - m0));
            Ps[rq0 * 72 + nt * 8 + p1]       = rnd(__expf(s[nt][1] - m0));
            Ps[(rq0 + 8) * 72 + nt * 8 + p0] = rnd(__expf(s[nt][2] - m1));
            Ps[(rq0 + 8) * 72 + nt * 8 + p1] = rnd(__expf(s[nt][3] - m1));
        }
        __syncwarp();
    }

    // ---- final deferred PV(nkt-1) ----
    {
        float* Vp = ((nkt - 1) & 1) ? VsB : VsA;
#pragma unroll
        for (int dt = 0; dt < 8; dt++) {
            o[dt][0] *= sc0s; o[dt][1] *= sc0s;
            o[dt][2] *= sc1s; o[dt][3] *= sc1s;
        }
        ol[0] *= sc0s; ol[1] *= sc0s; ol[2] *= sc1s; ol[3] *= sc1s;
#pragma unroll
        for (int ks = 0; ks < 8; ks++) {
            const int kcol = ks * 8 + 2 * tig;
            float2 u = *(const float2*)&Ps[rq0 * 72 + kcol];
            float2 w = *(const float2*)&Ps[(rq0 + 8) * 72 + kcol];
            uint32_t a[4] = {fu(u.x), fu(w.x), fu(u.y), fu(w.y)};
#pragma unroll
            for (int dt = 0; dt < 8; dt++) {
                float2 bv = *(const float2*)&Vp[(dt * 8 + gid) * 72 + kcol];
                uint32_t bb[2] = {fu(bv.x), fu(bv.y)};
                mma8(o[dt], a, bb);
            }
            mma8(ol, a, oneb);
        }
    }

    // Epilogue: write g_AO in k-permuted layout (matches g_Wor for gemm_out)
    const float il0 = 1.f / ol[0], il1 = 1.f / ol[2];
    const int qr0 = qb + rq0, qr1 = qb + rq0 + 8;
#pragma unroll
    for (int dt = 0; dt < 8; dt++) {
        int base = h * DH + dt * 8;
        if (qr0 < LQ) {
            g_AO[(size_t)qr0 * DM + base + p0] = rnd(o[dt][0] * il0);
            g_AO[(size_t)qr0 * DM + base + p1] = rnd(o[dt][1] * il0);
        }
        if (qr1 < LQ) {
            g_AO[(size_t)qr1 * DM + base + p0] = rnd(o[dt][2] * il1);
            g_AO[(size_t)qr1 * DM + base + p1] = rnd(o[dt][3] * il1);
        }
    }
}

// ============================================================================
extern "C" void kernel_launch(void* const* d_in, const int* in_sizes, int n_in,
                              void* d_out, int out_size) {
    const float* x     = (const float*)d_in[0];
    const float* W_S   = (const float*)d_in[1];
    const float* W_NS  = (const float*)d_in[2];
    const float* W_out = (const float*)d_in[3];
    float* out = (float*)d_out;
    (void)in_sizes; (void)n_in; (void)out_size;

    const int gemm_smem = 4 * 6144 * (int)sizeof(float);   // 98304
    const int attn_smem = 27648 * (int)sizeof(float);      // 110592

    cudaFuncSetAttribute(fused_qkv,   cudaFuncAttributeMaxDynamicSharedMemorySize, gemm_smem);
    cudaFuncSetAttribute(gemm_out,    cudaFuncAttributeMaxDynamicSharedMemorySize, gemm_smem);
    cudaFuncSetAttribute(attn_kernel, cudaFuncAttributeMaxDynamicSharedMemorySize, attn_smem);

    // 0) prep: round+permute x; transpose+round+permute W_S, W_out; zero d_out
    prep_x<<<512, 256>>>(x);
    prep_tr<<<dim3(3 * DM / 32, DM / 32), 256>>>(W_S, 0);
    prep_tr<<<dim3(DM / 32, DM / 32), 256>>>(W_out, 1);
    zeroC<<<(LQ * DM / 4 + 255) / 256, 256>>>(out);

    // 1+2) fused: live qkv GEMM tiles (640, K permuted in epilogue) + NS (192)
    fused_qkv<<<832, 256, gemm_smem>>>(x, W_NS);

    // 2b) repack V (transpose + token-permute)
    repack_Vt<<<dim3(LK / 32, DM / 32), 256>>>();

    // 3) attention: 17 q-pair tiles x 16 heads, longest first
    attn_kernel<<<17 * NH, 256, attn_smem>>>();

    // 4) output projection, split-K x2, atomic accumulate
    gemm_out<<<dim3(1024 / 128, (LQ + 127) / 128, 2), 256, gemm_smem>>>(out);
}

// round 13
// speedup vs baseline: 1.3173x; 1.3173x over previous
#include <cuda_runtime.h>
#include <cuda_fp16.h>
#include <cstdint>
#include <cstddef>

// Problem constants
#define L_S_C   4096
#define QSTART  2048
#define L_NS_C  64
#define LQ      2112
#define LK      4160
#define DM      1024
#define NH      16
#define DH      64

// Scratch (device globals, fp16 except where noted). g_Q padded +64 rows.
__device__ __align__(16) __half g_Q[(size_t)(LQ + 64) * DM];   // d 16-blk permuted, pre-scaled 0.125
__device__ __align__(16) __half g_V[(size_t)LK * DM];          // plain [token][d]
__device__ __align__(16) __half g_AO[(size_t)LQ * DM];         // k 16-blk permuted
__device__ __align__(16) __half g_xr[(size_t)LK * DM];         // x, k 16-blk permuted
__device__ __align__(16) __half g_Wsr[(size_t)(3 * DM) * DM];  // W_S^T [n][k], permuted
__device__ __align__(16) __half g_Wor[(size_t)DM * DM];        // W_out^T [n][k], permuted
__device__ __align__(16) __half g_Kp[(size_t)LK * DM];         // K, d 16-blk permuted
__device__ __align__(16) __half g_Vt[(size_t)DM * LK];         // V^T [d][token], token permuted

// 16-block permutation: stored pos 4t..4t+3 hold orig k = 2t, 2t+1, 2t+8, 2t+9.
__device__ __forceinline__ int perm16(int c) {
    return (c < 8) ? (4 * (c >> 1) + (c & 1)) : (4 * ((c - 8) >> 1) + 2 + (c & 1));
}

__device__ __forceinline__ uint32_t h2u(float a, float b) {
    __half2 h = __floats2half2_rn(a, b);
    return *reinterpret_cast<uint32_t*>(&h);
}

__device__ __forceinline__ void mma16(float* c, const uint32_t* a, const uint32_t* b) {
    asm volatile(
        "mma.sync.aligned.m16n8k16.row.col.f32.f16.f16.f32 "
        "{%0,%1,%2,%3}, {%4,%5,%6,%7}, {%8,%9}, {%0,%1,%2,%3};\n"
        : "+f"(c[0]), "+f"(c[1]), "+f"(c[2]), "+f"(c[3])
        : "r"(a[0]), "r"(a[1]), "r"(a[2]), "r"(a[3]), "r"(b[0]), "r"(b[1]));
}

__device__ __forceinline__ void cp16(void* dst, const void* src, int sz) {
    uint32_t d = (uint32_t)__cvta_generic_to_shared(dst);
    asm volatile("cp.async.cg.shared.global [%0], [%1], 16, %2;\n"
                 :: "r"(d), "l"(src), "r"(sz));
}
#define CP_COMMIT()  asm volatile("cp.async.commit_group;\n")
#define CP_WAIT(n)   asm volatile("cp.async.wait_group %0;\n" :: "n"(n))

// ============================================================================
// Prep: x -> fp16 permuted; W_S/W_out -> transpose + fp16 + permuted.
// ============================================================================
__global__ void __launch_bounds__(256)
prep_x(const float* __restrict__ x) {
    const int NB = (int)((size_t)LK * DM / 16);
    for (int i = blockIdx.x * blockDim.x + threadIdx.x; i < NB;
         i += gridDim.x * blockDim.x) {
        const float4* f = (const float4*)(x + (size_t)i * 16);
        float4 f0 = f[0], f1 = f[1], f2 = f[2], f3 = f[3];
        uint4 w0, w1;
        w0.x = h2u(f0.x, f0.y);  w0.y = h2u(f2.x, f2.y);
        w0.z = h2u(f0.z, f0.w);  w0.w = h2u(f2.z, f2.w);
        w1.x = h2u(f1.x, f1.y);  w1.y = h2u(f3.x, f3.y);
        w1.z = h2u(f1.z, f1.w);  w1.w = h2u(f3.z, f3.w);
        *(uint4*)&g_xr[(size_t)i * 16]     = w0;
        *(uint4*)&g_xr[(size_t)i * 16 + 8] = w1;
    }
}

__global__ void __launch_bounds__(256)
prep_tr(const float* __restrict__ src, int which) {
    __shared__ float t[32][33];
    const int C = which ? DM : 3 * DM;
    __half* dst = which ? g_Wor : g_Wsr;
    const int c0 = blockIdx.x * 32, r0 = blockIdx.y * 32;
    const int tx = threadIdx.x & 31, ty = threadIdx.x >> 5;
#pragma unroll
    for (int i = 0; i < 4; i++)
        t[ty + i * 8][tx] = src[(size_t)(r0 + ty + i * 8) * C + c0 + tx];
    __syncthreads();
    const int pk = r0 + (tx & ~15) + perm16(tx & 15);
#pragma unroll
    for (int i = 0; i < 4; i++)
        dst[(size_t)(c0 + ty + i * 8) * DM + pk] = __float2half_rn(t[tx][ty + i * 8]);
}

// V transpose repack: fp16 [d][token], token 16-block permuted.
__global__ void __launch_bounds__(256)
repack_Vt() {
    __shared__ __half t[32][34];
    const int tok0 = blockIdx.x * 32, d0 = blockIdx.y * 32;
    const int tx = threadIdx.x & 31, ty = threadIdx.x >> 5;
#pragma unroll
    for (int i = 0; i < 4; i++)
        t[ty + i * 8][tx] = g_V[(size_t)(tok0 + ty + i * 8) * DM + d0 + tx];
    __syncthreads();
    const int ptok = tok0 + (tx & ~15) + perm16(tx & 15);
#pragma unroll
    for (int i = 0; i < 4; i++)
        g_Vt[(size_t)(d0 + ty + i * 8) * LK + ptok] = t[tx][ty + i * 8];
}

__global__ void __launch_bounds__(256)
zeroC(float* __restrict__ C) {
    int i = blockIdx.x * blockDim.x + threadIdx.x;
    if (i < LQ * DM / 4) ((float4*)C)[i] = make_float4(0.f, 0.f, 0.f, 0.f);
}

// ============================================================================
// fp16 warp-MMA GEMM tile (m16n8k16): k-chunk 64, 2 stages, 1 barrier/iter.
// smem halves: As0 @0, As1 @9216, Bs0 @18432, Bs1 @27648 (stride 72 halves).
// MODE 0: scatter half2 into g_Q(scaled,perm)/g_Kp(perm)/g_V. MODE 1: atomicAdd.
// ============================================================================
template <int MODE>
__device__ __forceinline__ void gemm_tile(const __half* __restrict__ A,
                                          const __half* __restrict__ Bt,
                                          float* __restrict__ C,
                                          int M, int N, int Ks, int kBeg, int kLen,
                                          int mBase, int nBase, __half* sm) {
    __half* As0 = sm;
    __half* As1 = sm + 9216;
    __half* Bs0 = sm + 18432;
    __half* Bs1 = sm + 27648;

    const int tid  = threadIdx.x;
    const int warp = tid >> 5, lane = tid & 31;
    const int gid  = lane >> 2, tig = lane & 3;
    const int wm = (warp >> 2) * 64;
    const int wn = (warp & 3) * 32;

    float c[4][4][4];
#pragma unroll
    for (int i = 0; i < 4; i++)
#pragma unroll
        for (int j = 0; j < 4; j++)
#pragma unroll
            for (int e = 0; e < 4; e++) c[i][j][e] = 0.f;

    auto issue = [&](int k0, __half* As, __half* Bs) {
#pragma unroll
        for (int i = 0; i < 4; i++) {
            int ch  = tid + i * 256;        // 0..1023
            int row = ch >> 3;
            int cc  = (ch & 7) * 8;
            int grow = mBase + row;
            int ok = (MODE == 1) ? (grow < M) : 1;
            cp16(&As[row * 72 + cc], A + (size_t)(ok ? grow : 0) * Ks + k0 + cc,
                 ok ? 16 : 0);
            cp16(&Bs[row * 72 + cc], Bt + (size_t)(nBase + row) * Ks + k0 + cc, 16);
        }
        CP_COMMIT();
    };

    issue(kBeg, As0, Bs0);

    const int T = kLen / 64;
    for (int t = 0; t < T; t++) {
        CP_WAIT(0);
        __syncthreads();
        if (t + 1 < T)
            issue(kBeg + (t + 1) * 64, (t & 1) ? As0 : As1, (t & 1) ? Bs0 : Bs1);
        __half* As = (t & 1) ? As1 : As0;
        __half* Bs = (t & 1) ? Bs1 : Bs0;

#pragma unroll
        for (int ks = 0; ks < 4; ks++) {
            const int off = ks * 16 + 4 * tig;
            uint32_t a[4][4];
#pragma unroll
            for (int mt = 0; mt < 4; mt++) {
                int r = wm + mt * 16 + gid;
                uint2 u0 = *(const uint2*)&As[r * 72 + off];
                uint2 u1 = *(const uint2*)&As[(r + 8) * 72 + off];
                a[mt][0] = u0.x; a[mt][1] = u1.x; a[mt][2] = u0.y; a[mt][3] = u1.y;
            }
            uint32_t b[4][2];
#pragma unroll
            for (int nt = 0; nt < 4; nt++) {
                int rn = wn + nt * 8 + gid;
                uint2 v = *(const uint2*)&Bs[rn * 72 + off];
                b[nt][0] = v.x; b[nt][1] = v.y;
            }
#pragma unroll
            for (int mt = 0; mt < 4; mt++)
#pragma unroll
                for (int nt = 0; nt < 4; nt++)
                    mma16(c[mt][nt], a[mt], b[nt]);
        }
    }

#pragma unroll
    for (int mt = 0; mt < 4; mt++) {
#pragma unroll
        for (int nt = 0; nt < 4; nt++) {
            int row0 = mBase + wm + mt * 16 + gid;
            int row1 = row0 + 8;
            int col  = nBase + wn + nt * 8 + 2 * tig;
            float v0 = c[mt][nt][0], v1 = c[mt][nt][1];
            float v2 = c[mt][nt][2], v3 = c[mt][nt][3];
            if (MODE == 0) {
                if (col < DM) {
                    int db = col & ~15, p = perm16(col & 15);
                    if (row0 >= QSTART)
                        *(uint32_t*)&g_Q[(size_t)(row0 - QSTART) * DM + db + p] =
                            h2u(v0 * 0.125f, v1 * 0.125f);
                    if (row1 >= QSTART)
                        *(uint32_t*)&g_Q[(size_t)(row1 - QSTART) * DM + db + p] =
                            h2u(v2 * 0.125f, v3 * 0.125f);
                } else if (col < 2 * DM) {
                    int ck = col - DM;
                    int db = ck & ~15, p = perm16(ck & 15);
                    *(uint32_t*)&g_Kp[(size_t)row0 * DM + db + p] = h2u(v0, v1);
                    *(uint32_t*)&g_Kp[(size_t)row1 * DM + db + p] = h2u(v2, v3);
                } else {
                    int cv = col - 2 * DM;
                    *(uint32_t*)&g_V[(size_t)row0 * DM + cv] = h2u(v0, v1);
                    *(uint32_t*)&g_V[(size_t)row1 * DM + cv] = h2u(v2, v3);
                }
            } else {
                if (row0 < M) {
                    atomicAdd(&C[(size_t)row0 * N + col], v0);
                    atomicAdd(&C[(size_t)row0 * N + col + 1], v1);
                }
                if (row1 < M) {
                    atomicAdd(&C[(size_t)row1 * N + col], v2);
                    atomicAdd(&C[(size_t)row1 * N + col + 1], v3);
                }
            }
        }
    }
}

// ============================================================================
// Fused qkv: 640 live GEMM tiles + 192 NS streaming blocks (10:3 interleave).
// ============================================================================
extern __shared__ char dynsm[];

__global__ void __launch_bounds__(256, 2)
fused_qkv(const float* __restrict__ x, const float* __restrict__ W_NS) {
    const int bid = blockIdx.x;
    const int grp = bid / 13, rem = bid % 13;
    if (rem < 10) {
        const int g = grp * 10 + rem;       // 0..639
        int mt, nt;
        if (g < 384) { mt = 16 + g / 24; nt = g % 24; }            // rows>=2048: QKV
        else { int g2 = g - 384; mt = g2 / 16; nt = 8 + g2 % 16; } // rows<2048: KV only
        gemm_tile<0>((const __half*)g_xr, (const __half*)g_Wsr, nullptr,
                     4096, 3072, 1024, 0, 1024, mt * 128, nt * 128, (__half*)dynsm);
    } else {
        float* xs = (float*)dynsm;
        const int ns  = grp * 3 + (rem - 10);   // 0..191
        const int tok = ns / 3;
        const int cb  = ns % 3;                 // 0=Q, 1=K, 2=V
        const int c4  = cb * 1024 + threadIdx.x * 4;

        const float* xr = x + (size_t)(L_S_C + tok) * DM;
        for (int i = threadIdx.x; i < DM; i += 256) xs[i] = xr[i];
        __syncthreads();

        const float* Wp = W_NS + (size_t)tok * DM * 3072 + c4;
        float4 acc = make_float4(0.f, 0.f, 0.f, 0.f);
#pragma unroll 8
        for (int d = 0; d < DM; d++) {
            float4 w = __ldcs((const float4*)(Wp + (size_t)d * 3072));
            float xv = xs[d];
            acc.x = fmaf(xv, w.x, acc.x);
            acc.y = fmaf(xv, w.y, acc.y);
            acc.z = fmaf(xv, w.z, acc.z);
            acc.w = fmaf(xv, w.w, acc.w);
        }

        if (cb == 0) {
            int db = c4 & ~15, c16 = c4 & 15;
            __half* qd = g_Q + (size_t)(QSTART + tok) * DM + db;
            *(uint32_t*)&qd[perm16(c16)]     = h2u(acc.x * 0.125f, acc.y * 0.125f);
            *(uint32_t*)&qd[perm16(c16 + 2)] = h2u(acc.z * 0.125f, acc.w * 0.125f);
        } else if (cb == 1) {
            int ck = c4 - 1024;
            int db = ck & ~15, c16 = ck & 15;
            __half* kd = g_Kp + (size_t)(L_S_C + tok) * DM + db;
            *(uint32_t*)&kd[perm16(c16)]     = h2u(acc.x, acc.y);
            *(uint32_t*)&kd[perm16(c16 + 2)] = h2u(acc.z, acc.w);
        } else {
            uint2 w; w.x = h2u(acc.x, acc.y); w.y = h2u(acc.z, acc.w);
            *(uint2*)&g_V[(size_t)(L_S_C + tok) * DM + (c4 - 2048)] = w;
        }
    }
}

// Output projection, split-K x2, atomicAdd epilogue.
__global__ void __launch_bounds__(256, 2)
gemm_out(float* __restrict__ C) {
    gemm_tile<1>((const __half*)g_AO, (const __half*)g_Wor, C, LQ, 1024, 1024,
                 blockIdx.z * 512, 512, blockIdx.y * 128, blockIdx.x * 128,
                 (__half*)dynsm);
}

// ============================================================================
// Flash attention v7 (fp16): 128 q-rows/CTA, 256 thr / 8 warps. Q frags in
// regs (LDG direct, pre-scaled/permuted). P stays in REGISTERS (the m16n8k16
// A-fragment equals the S accumulator ownership). Deferred-PV pipeline.
// smem: 4 KV buffers [64][72] halves = 36 KB.
// ============================================================================
__global__ void __launch_bounds__(256, 2)
attn_kernel() {
    __half* KsA = (__half*)dynsm;          // [64][72]
    __half* KsB = (__half*)dynsm + 4608;
    __half* VsA = (__half*)dynsm + 9216;
    __half* VsB = (__half*)dynsm + 13824;

    const int qtp = 16 - ((int)blockIdx.x >> 4);   // descending work size
    const int h   = blockIdx.x & 15;
    const int qb  = qtp * 128;
    const int tid  = threadIdx.x;
    const int warp = tid >> 5, lane = tid & 31;
    const int gid  = lane >> 2, tig = lane & 3;
    const int rq0  = warp * 16 + gid;

    auto loadKV = [&](int kt, __half* Kd, __half* Vd) {
        const __half* kp = g_Kp + (size_t)kt * 64 * DM + h * DH;
        const __half* vp = g_Vt + (size_t)h * DH * LK + (size_t)kt * 64;
#pragma unroll
        for (int i = 0; i < 2; i++) {
            int ch = tid + i * 256;        // 0..511
            int r = ch >> 3, cc = (ch & 7) * 8;
            cp16(&Kd[r * 72 + cc], kp + (size_t)r * DM + cc, 16);
            cp16(&Vd[r * 72 + cc], vp + (size_t)r * LK + cc, 16);
        }
        CP_COMMIT();
    };

    loadKV(0, KsA, VsA);

    // Q fragments straight from gmem (pre-scaled, permuted).
    uint32_t qa[4][4];
    {
        const __half* q0 = g_Q + (size_t)(qb + rq0) * DM + h * DH;
        const __half* q1 = g_Q + (size_t)(qb + rq0 + 8) * DM + h * DH;
#pragma unroll
        for (int ks = 0; ks < 4; ks++) {
            uint2 u0 = *(const uint2*)(q0 + ks * 16 + 4 * tig);
            uint2 u1 = *(const uint2*)(q1 + ks * 16 + 4 * tig);
            qa[ks][0] = u0.x; qa[ks][1] = u1.x; qa[ks][2] = u0.y; qa[ks][3] = u1.y;
        }
    }

    float m0 = -1e30f, m1 = -1e30f, l0 = 0.f, l1 = 0.f;
    float sc0s = 0.f, sc1s = 0.f;
    uint32_t pa[4][4];                 // P(kt-1) as fp16 A-fragments
    float o[8][4];
#pragma unroll
    for (int i = 0; i < 8; i++)
#pragma unroll
        for (int e = 0; e < 4; e++) o[i][e] = 0.f;

    const int nktFull = 34 + 2 * qtp;
    const int nkt = nktFull < 65 ? nktFull : 65;
    for (int kt = 0; kt < nkt; kt++) {
        CP_WAIT(0);
        __syncthreads();

        __half* Ks = (kt & 1) ? KsB : KsA;

        // ---- S(kt) = Q @ K^T ----
        float s[8][4];
#pragma unroll
        for (int i = 0; i < 8; i++)
#pragma unroll
            for (int e = 0; e < 4; e++) s[i][e] = 0.f;

#pragma unroll
        for (int ks = 0; ks < 4; ks++) {
            const int off = ks * 16 + 4 * tig;
#pragma unroll
            for (int nt = 0; nt < 8; nt++) {
                uint2 kv = *(const uint2*)&Ks[(nt * 8 + gid) * 72 + off];
                uint32_t bb[2] = {kv.x, kv.y};
                mma16(s[nt], qa[ks], bb);
            }
        }

        // ---- deferred PV(kt-1) ----
        if (kt > 0) {
            __half* Vp = (kt & 1) ? VsA : VsB;
#pragma unroll
            for (int dt = 0; dt < 8; dt++) {
                o[dt][0] *= sc0s; o[dt][1] *= sc0s;
                o[dt][2] *= sc1s; o[dt][3] *= sc1s;
            }
#pragma unroll
            for (int g = 0; g < 4; g++) {
                const int off = g * 16 + 4 * tig;
#pragma unroll
                for (int dt = 0; dt < 8; dt++) {
                    uint2 vv = *(const uint2*)&Vp[(dt * 8 + gid) * 72 + off];
                    uint32_t bb[2] = {vv.x, vv.y};
                    mma16(o[dt], pa[g], bb);
                }
            }
        }

        __syncthreads();
        if (kt + 1 < nkt)
            loadKV(kt + 1, (kt & 1) ? KsA : KsB, (kt & 1) ? VsA : VsB);

        // ---- causal mask on last two k-tiles ----
        if (kt >= nkt - 2) {
            const int off = kt * 64 - QSTART - qb;
#pragma unroll
            for (int nt = 0; nt < 8; nt++) {
#pragma unroll
                for (int e = 0; e < 4; e++) {
                    int kc  = nt * 8 + 2 * tig + (e & 1);
                    int rit = warp * 16 + gid + ((e >> 1) << 3);
                    if (kc + off > rit) s[nt][e] = -1e30f;
                }
            }
        }

        // ---- online softmax(kt) ----
        float rm0 = -1e30f, rm1 = -1e30f;
#pragma unroll
        for (int nt = 0; nt < 8; nt++) {
            rm0 = fmaxf(rm0, fmaxf(s[nt][0], s[nt][1]));
            rm1 = fmaxf(rm1, fmaxf(s[nt][2], s[nt][3]));
        }
        rm0 = fmaxf(rm0, __shfl_xor_sync(0xffffffffu, rm0, 1));
        rm0 = fmaxf(rm0, __shfl_xor_sync(0xffffffffu, rm0, 2));
        rm1 = fmaxf(rm1, __shfl_xor_sync(0xffffffffu, rm1, 1));
        rm1 = fmaxf(rm1, __shfl_xor_sync(0xffffffffu, rm1, 2));

        float mn0 = fmaxf(m0, rm0), mn1 = fmaxf(m1, rm1);
        sc0s = __expf(m0 - mn0);
        sc1s = __expf(m1 - mn1);
        m0 = mn0; m1 = mn1;

        float rs0 = 0.f, rs1 = 0.f;
#pragma unroll
        for (int nt = 0; nt < 8; nt++) {
            s[nt][0] = __expf(s[nt][0] - m0); rs0 += s[nt][0];
            s[nt][1] = __expf(s[nt][1] - m0); rs0 += s[nt][1];
            s[nt][2] = __expf(s[nt][2] - m1); rs1 += s[nt][2];
            s[nt][3] = __expf(s[nt][3] - m1); rs1 += s[nt][3];
        }
        rs0 += __shfl_xor_sync(0xffffffffu, rs0, 1);
        rs0 += __shfl_xor_sync(0xffffffffu, rs0, 2);
        rs1 += __shfl_xor_sync(0xffffffffu, rs1, 1);
        rs1 += __shfl_xor_sync(0xffffffffu, rs1, 2);
        l0 = l0 * sc0s + rs0;
        l1 = l1 * sc1s + rs1;

        // ---- pack P(kt) into register A-fragments (no smem!) ----
#pragma unroll
        for (int g = 0; g < 4; g++) {
            pa[g][0] = h2u(s[2 * g][0], s[2 * g][1]);
            pa[g][1] = h2u(s[2 * g][2], s[2 * g][3]);
            pa[g][2] = h2u(s[2 * g + 1][0], s[2 * g + 1][1]);
            pa[g][3] = h2u(s[2 * g + 1][2], s[2 * g + 1][3]);
        }
    }

    // ---- final deferred PV(nkt-1) ----
    {
        __half* Vp = ((nkt - 1) & 1) ? VsB : VsA;
#pragma unroll
        for (int dt = 0; dt < 8; dt++) {
            o[dt][0] *= sc0s; o[dt][1] *= sc0s;
            o[dt][2] *= sc1s; o[dt][3] *= sc1s;
        }
#pragma unroll
        for (int g = 0; g < 4; g++) {
            const int off = g * 16 + 4 * tig;
#pragma unroll
            for (int dt = 0; dt < 8; dt++) {
                uint2 vv = *(const uint2*)&Vp[(dt * 8 + gid) * 72 + off];
                uint32_t bb[2] = {vv.x, vv.y};
                mma16(o[dt], pa[g], bb);
            }
        }
    }

    // Epilogue: g_AO fp16, k 16-block permuted (matches g_Wor).
    const float il0 = 1.f / l0, il1 = 1.f / l1;
    const int qr0 = qb + rq0, qr1 = qb + rq0 + 8;
#pragma unroll
    for (int dt = 0; dt < 8; dt++) {
        int col = h * DH + dt * 8 + 2 * tig;
        int db = col & ~15, p = perm16(col & 15);
        if (qr0 < LQ)
            *(uint32_t*)&g_AO[(size_t)qr0 * DM + db + p] =
                h2u(o[dt][0] * il0, o[dt][1] * il0);
        if (qr1 < LQ)
            *(uint32_t*)&g_AO[(size_t)qr1 * DM + db + p] =
                h2u(o[dt][2] * il1, o[dt][3] * il1);
    }
}

// ============================================================================
extern "C" void kernel_launch(void* const* d_in, const int* in_sizes, int n_in,
                              void* d_out, int out_size) {
    const float* x     = (const float*)d_in[0];
    const float* W_S   = (const float*)d_in[1];
    const float* W_NS  = (const float*)d_in[2];
    const float* W_out = (const float*)d_in[3];
    float* out = (float*)d_out;
    (void)in_sizes; (void)n_in; (void)out_size;

    const int gemm_smem = 36864 * 2;   // 73728 B (4 stages-of-2 x 9216 halves)
    const int attn_smem = 18432 * 2;   // 36864 B

    cudaFuncSetAttribute(fused_qkv,   cudaFuncAttributeMaxDynamicSharedMemorySize, gemm_smem);
    cudaFuncSetAttribute(gemm_out,    cudaFuncAttributeMaxDynamicSharedMemorySize, gemm_smem);
    cudaFuncSetAttribute(attn_kernel, cudaFuncAttributeMaxDynamicSharedMemorySize, attn_smem);

    // 0) prep: x/W_S/W_out -> fp16 permuted; zero d_out
    prep_x<<<512, 256>>>(x);
    prep_tr<<<dim3(3 * DM / 32, DM / 32), 256>>>(W_S, 0);
    prep_tr<<<dim3(DM / 32, DM / 32), 256>>>(W_out, 1);
    zeroC<<<(LQ * DM / 4 + 255) / 256, 256>>>(out);

    // 1+2) fused: live qkv GEMM tiles (640) + NS streaming (192)
    fused_qkv<<<832, 256, gemm_smem>>>(x, W_NS);

    // 2b) repack V (transpose + token 16-blk permute)
    repack_Vt<<<dim3(LK / 32, DM / 32), 256>>>();

    // 3) attention: 17 q-pair tiles x 16 heads, longest first
    attn_kernel<<<17 * NH, 256, attn_smem>>>();

    // 4) output projection, split-K x2, atomic accumulate
    gemm_out<<<dim3(1024 / 128, (LQ + 127) / 128, 2), 256, gemm_smem>>>(out);
}

// round 14
// speedup vs baseline: 1.3466x; 1.0222x over previous
#include <cuda_runtime.h>
#include <cuda_fp16.h>
#include <cstdint>
#include <cstddef>

// Problem constants
#define L_S_C   4096
#define QSTART  2048
#define L_NS_C  64
#define LQ      2112
#define LK      4160
#define DM      1024
#define NH      16
#define DH      64

// Q pre-scale: Dh^-0.5 * log2(e)  (softmax runs in exp2 domain)
#define QSC     0.18033688011f

// Scratch (device globals, fp16 except where noted). g_Q padded +64 rows.
__device__ __align__(16) __half g_Q[(size_t)(LQ + 64) * DM];   // d 16-blk permuted, pre-scaled QSC
__device__ __align__(16) __half g_V[(size_t)LK * DM];          // plain [token][d]
__device__ __align__(16) __half g_AO[(size_t)LQ * DM];         // k 16-blk permuted
__device__ __align__(16) __half g_xr[(size_t)LK * DM];         // x, k 16-blk permuted
__device__ __align__(16) __half g_Wsr[(size_t)(3 * DM) * DM];  // W_S^T [n][k], permuted
__device__ __align__(16) __half g_Wor[(size_t)DM * DM];        // W_out^T [n][k], permuted
__device__ __align__(16) __half g_Kp[(size_t)LK * DM];         // K, d 16-blk permuted
__device__ __align__(16) __half g_Vt[(size_t)DM * LK];         // V^T [d][token], token permuted

// 16-block permutation: stored pos 4t..4t+3 hold orig k = 2t, 2t+1, 2t+8, 2t+9.
__device__ __forceinline__ int perm16(int c) {
    return (c < 8) ? (4 * (c >> 1) + (c & 1)) : (4 * ((c - 8) >> 1) + 2 + (c & 1));
}

__device__ __forceinline__ uint32_t h2u(float a, float b) {
    __half2 h = __floats2half2_rn(a, b);
    return *reinterpret_cast<uint32_t*>(&h);
}

__device__ __forceinline__ void mma16(float* c, const uint32_t* a, const uint32_t* b) {
    asm volatile(
        "mma.sync.aligned.m16n8k16.row.col.f32.f16.f16.f32 "
        "{%0,%1,%2,%3}, {%4,%5,%6,%7}, {%8,%9}, {%0,%1,%2,%3};\n"
        : "+f"(c[0]), "+f"(c[1]), "+f"(c[2]), "+f"(c[3])
        : "r"(a[0]), "r"(a[1]), "r"(a[2]), "r"(a[3]), "r"(b[0]), "r"(b[1]));
}

__device__ __forceinline__ void cp16(void* dst, const void* src, int sz) {
    uint32_t d = (uint32_t)__cvta_generic_to_shared(dst);
    asm volatile("cp.async.cg.shared.global [%0], [%1], 16, %2;\n"
                 :: "r"(d), "l"(src), "r"(sz));
}
#define CP_COMMIT()  asm volatile("cp.async.commit_group;\n")
#define CP_WAIT(n)   asm volatile("cp.async.wait_group %0;\n" :: "n"(n))

// ============================================================================
// Prep: x -> fp16 permuted; W_S/W_out -> transpose + fp16 + permuted.
// ============================================================================
__global__ void __launch_bounds__(256)
prep_x(const float* __restrict__ x) {
    const int NB = (int)((size_t)LK * DM / 16);
    for (int i = blockIdx.x * blockDim.x + threadIdx.x; i < NB;
         i += gridDim.x * blockDim.x) {
        const float4* f = (const float4*)(x + (size_t)i * 16);
        float4 f0 = f[0], f1 = f[1], f2 = f[2], f3 = f[3];
        uint4 w0, w1;
        w0.x = h2u(f0.x, f0.y);  w0.y = h2u(f2.x, f2.y);
        w0.z = h2u(f0.z, f0.w);  w0.w = h2u(f2.z, f2.w);
        w1.x = h2u(f1.x, f1.y);  w1.y = h2u(f3.x, f3.y);
        w1.z = h2u(f1.z, f1.w);  w1.w = h2u(f3.z, f3.w);
        *(uint4*)&g_xr[(size_t)i * 16]     = w0;
        *(uint4*)&g_xr[(size_t)i * 16 + 8] = w1;
    }
}

__global__ void __launch_bounds__(256)
prep_tr(const float* __restrict__ src, int which) {
    __shared__ float t[32][33];
    const int C = which ? DM : 3 * DM;
    __half* dst = which ? g_Wor : g_Wsr;
    const int c0 = blockIdx.x * 32, r0 = blockIdx.y * 32;
    const int tx = threadIdx.x & 31, ty = threadIdx.x >> 5;
#pragma unroll
    for (int i = 0; i < 4; i++)
        t[ty + i * 8][tx] = src[(size_t)(r0 + ty + i * 8) * C + c0 + tx];
    __syncthreads();
    const int pk = r0 + (tx & ~15) + perm16(tx & 15);
#pragma unroll
    for (int i = 0; i < 4; i++)
        dst[(size_t)(c0 + ty + i * 8) * DM + pk] = __float2half_rn(t[tx][ty + i * 8]);
}

// V transpose repack: fp16 [d][token], token 16-block permuted.
__global__ void __launch_bounds__(256)
repack_Vt() {
    __shared__ __half t[32][34];
    const int tok0 = blockIdx.x * 32, d0 = blockIdx.y * 32;
    const int tx = threadIdx.x & 31, ty = threadIdx.x >> 5;
#pragma unroll
    for (int i = 0; i < 4; i++)
        t[ty + i * 8][tx] = g_V[(size_t)(tok0 + ty + i * 8) * DM + d0 + tx];
    __syncthreads();
    const int ptok = tok0 + (tx & ~15) + perm16(tx & 15);
#pragma unroll
    for (int i = 0; i < 4; i++)
        g_Vt[(size_t)(d0 + ty + i * 8) * LK + ptok] = t[tx][ty + i * 8];
}

// ============================================================================
// fp16 warp-MMA GEMM tile (m16n8k16): k-chunk 64, 2 stages, 1 barrier/iter.
// smem halves: As0 @0, As1 @9216, Bs0 @18432, Bs1 @27648 (stride 72 halves).
// MODE 0: scatter half2 into g_Q(scaled,perm)/g_Kp(perm)/g_V. MODE 1: store C.
// ============================================================================
template <int MODE>
__device__ __forceinline__ void gemm_tile(const __half* __restrict__ A,
                                          const __half* __restrict__ Bt,
                                          float* __restrict__ C,
                                          int M, int N, int Ks, int kBeg, int kLen,
                                          int mBase, int nBase, __half* sm) {
    __half* As0 = sm;
    __half* As1 = sm + 9216;
    __half* Bs0 = sm + 18432;
    __half* Bs1 = sm + 27648;

    const int tid  = threadIdx.x;
    const int warp = tid >> 5, lane = tid & 31;
    const int gid  = lane >> 2, tig = lane & 3;
    const int wm = (warp >> 2) * 64;
    const int wn = (warp & 3) * 32;

    float c[4][4][4];
#pragma unroll
    for (int i = 0; i < 4; i++)
#pragma unroll
        for (int j = 0; j < 4; j++)
#pragma unroll
            for (int e = 0; e < 4; e++) c[i][j][e] = 0.f;

    auto issue = [&](int k0, __half* As, __half* Bs) {
#pragma unroll
        for (int i = 0; i < 4; i++) {
            int ch  = tid + i * 256;        // 0..1023
            int row = ch >> 3;
            int cc  = (ch & 7) * 8;
            int grow = mBase + row;
            int ok = (MODE == 1) ? (grow < M) : 1;
            cp16(&As[row * 72 + cc], A + (size_t)(ok ? grow : 0) * Ks + k0 + cc,
                 ok ? 16 : 0);
            cp16(&Bs[row * 72 + cc], Bt + (size_t)(nBase + row) * Ks + k0 + cc, 16);
        }
        CP_COMMIT();
    };

    issue(kBeg, As0, Bs0);

    const int T = kLen / 64;
    for (int t = 0; t < T; t++) {
        CP_WAIT(0);
        __syncthreads();
        if (t + 1 < T)
            issue(kBeg + (t + 1) * 64, (t & 1) ? As0 : As1, (t & 1) ? Bs0 : Bs1);
        __half* As = (t & 1) ? As1 : As0;
        __half* Bs = (t & 1) ? Bs1 : Bs0;

#pragma unroll
        for (int ks = 0; ks < 4; ks++) {
            const int off = ks * 16 + 4 * tig;
            uint32_t a[4][4];
#pragma unroll
            for (int mt = 0; mt < 4; mt++) {
                int r = wm + mt * 16 + gid;
                uint2 u0 = *(const uint2*)&As[r * 72 + off];
                uint2 u1 = *(const uint2*)&As[(r + 8) * 72 + off];
                a[mt][0] = u0.x; a[mt][1] = u1.x; a[mt][2] = u0.y; a[mt][3] = u1.y;
            }
            uint32_t b[4][2];
#pragma unroll
            for (int nt = 0; nt < 4; nt++) {
                int rn = wn + nt * 8 + gid;
                uint2 v = *(const uint2*)&Bs[rn * 72 + off];
                b[nt][0] = v.x; b[nt][1] = v.y;
            }
#pragma unroll
            for (int mt = 0; mt < 4; mt++)
#pragma unroll
                for (int nt = 0; nt < 4; nt++)
                    mma16(c[mt][nt], a[mt], b[nt]);
        }
    }

#pragma unroll
    for (int mt = 0; mt < 4; mt++) {
#pragma unroll
        for (int nt = 0; nt < 4; nt++) {
            int row0 = mBase + wm + mt * 16 + gid;
            int row1 = row0 + 8;
            int col  = nBase + wn + nt * 8 + 2 * tig;
            float v0 = c[mt][nt][0], v1 = c[mt][nt][1];
            float v2 = c[mt][nt][2], v3 = c[mt][nt][3];
            if (MODE == 0) {
                if (col < DM) {
                    int db = col & ~15, p = perm16(col & 15);
                    if (row0 >= QSTART)
                        *(uint32_t*)&g_Q[(size_t)(row0 - QSTART) * DM + db + p] =
                            h2u(v0 * QSC, v1 * QSC);
                    if (row1 >= QSTART)
                        *(uint32_t*)&g_Q[(size_t)(row1 - QSTART) * DM + db + p] =
                            h2u(v2 * QSC, v3 * QSC);
                } else if (col < 2 * DM) {
                    int ck = col - DM;
                    int db = ck & ~15, p = perm16(ck & 15);
                    *(uint32_t*)&g_Kp[(size_t)row0 * DM + db + p] = h2u(v0, v1);
                    *(uint32_t*)&g_Kp[(size_t)row1 * DM + db + p] = h2u(v2, v3);
                } else {
                    int cv = col - 2 * DM;
                    *(uint32_t*)&g_V[(size_t)row0 * DM + cv] = h2u(v0, v1);
                    *(uint32_t*)&g_V[(size_t)row1 * DM + cv] = h2u(v2, v3);
                }
            } else {
                if (row0 < M) *(float2*)&C[(size_t)row0 * N + col] = make_float2(v0, v1);
                if (row1 < M) *(float2*)&C[(size_t)row1 * N + col] = make_float2(v2, v3);
            }
        }
    }
}

// ============================================================================
// Fused qkv: 640 live GEMM tiles + 192 NS streaming blocks (10:3 interleave).
// ============================================================================
extern __shared__ char dynsm[];

__global__ void __launch_bounds__(256, 2)
fused_qkv(const float* __restrict__ x, const float* __restrict__ W_NS) {
    const int bid = blockIdx.x;
    const int grp = bid / 13, rem = bid % 13;
    if (rem < 10) {
        const int g = grp * 10 + rem;       // 0..639
        int mt, nt;
        if (g < 384) { mt = 16 + g / 24; nt = g % 24; }            // rows>=2048: QKV
        else { int g2 = g - 384; mt = g2 / 16; nt = 8 + g2 % 16; } // rows<2048: KV only
        gemm_tile<0>((const __half*)g_xr, (const __half*)g_Wsr, nullptr,
                     4096, 3072, 1024, 0, 1024, mt * 128, nt * 128, (__half*)dynsm);
    } else {
        float* xs = (float*)dynsm;
        const int ns  = grp * 3 + (rem - 10);   // 0..191
        const int tok = ns / 3;
        const int cb  = ns % 3;                 // 0=Q, 1=K, 2=V
        const int c4  = cb * 1024 + threadIdx.x * 4;

        const float* xr = x + (size_t)(L_S_C + tok) * DM;
        for (int i = threadIdx.x; i < DM; i += 256) xs[i] = xr[i];
        __syncthreads();

        const float* Wp = W_NS + (size_t)tok * DM * 3072 + c4;
        float4 acc = make_float4(0.f, 0.f, 0.f, 0.f);
#pragma unroll 8
        for (int d = 0; d < DM; d++) {
            float4 w = __ldcs((const float4*)(Wp + (size_t)d * 3072));
            float xv = xs[d];
            acc.x = fmaf(xv, w.x, acc.x);
            acc.y = fmaf(xv, w.y, acc.y);
            acc.z = fmaf(xv, w.z, acc.z);
            acc.w = fmaf(xv, w.w, acc.w);
        }

        if (cb == 0) {
            int db = c4 & ~15, c16 = c4 & 15;
            __half* qd = g_Q + (size_t)(QSTART + tok) * DM + db;
            *(uint32_t*)&qd[perm16(c16)]     = h2u(acc.x * QSC, acc.y * QSC);
            *(uint32_t*)&qd[perm16(c16 + 2)] = h2u(acc.z * QSC, acc.w * QSC);
        } else if (cb == 1) {
            int ck = c4 - 1024;
            int db = ck & ~15, c16 = ck & 15;
            __half* kd = g_Kp + (size_t)(L_S_C + tok) * DM + db;
            *(uint32_t*)&kd[perm16(c16)]     = h2u(acc.x, acc.y);
            *(uint32_t*)&kd[perm16(c16 + 2)] = h2u(acc.z, acc.w);
        } else {
            uint2 w; w.x = h2u(acc.x, acc.y); w.y = h2u(acc.z, acc.w);
            *(uint2*)&g_V[(size_t)(L_S_C + tok) * DM + (c4 - 2048)] = w;
        }
    }
}

// Output projection: full K, direct stores (no atomics / zero-fill needed).
__global__ void __launch_bounds__(256, 2)
gemm_out(float* __restrict__ C) {
    gemm_tile<1>((const __half*)g_AO, (const __half*)g_Wor, C, LQ, 1024, 1024,
                 0, 1024, blockIdx.y * 128, blockIdx.x * 128, (__half*)dynsm);
}

// ============================================================================
// Flash attention v8 (fp16): 128 q-rows/CTA, 256 thr / 8 warps. Q frags in
// regs (exp2-domain pre-scaled, permuted). P stays in registers. Deferred-PV.
// l accumulated via ones-column MMA (no sum reduction). exp2f softmax.
// smem: 4 KV buffers [64][72] halves = 36 KB.
// ============================================================================
__global__ void __launch_bounds__(256, 2)
attn_kernel() {
    __half* KsA = (__half*)dynsm;          // [64][72]
    __half* KsB = (__half*)dynsm + 4608;
    __half* VsA = (__half*)dynsm + 9216;
    __half* VsB = (__half*)dynsm + 13824;

    const int qtp = 16 - ((int)blockIdx.x >> 4);   // descending work size
    const int h   = blockIdx.x & 15;
    const int qb  = qtp * 128;
    const int tid  = threadIdx.x;
    const int warp = tid >> 5, lane = tid & 31;
    const int gid  = lane >> 2, tig = lane & 3;
    const int rq0  = warp * 16 + gid;

    auto loadKV = [&](int kt, __half* Kd, __half* Vd) {
        const __half* kp = g_Kp + (size_t)kt * 64 * DM + h * DH;
        const __half* vp = g_Vt + (size_t)h * DH * LK + (size_t)kt * 64;
#pragma unroll
        for (int i = 0; i < 2; i++) {
            int ch = tid + i * 256;        // 0..511
            int r = ch >> 3, cc = (ch & 7) * 8;
            cp16(&Kd[r * 72 + cc], kp + (size_t)r * DM + cc, 16);
            cp16(&Vd[r * 72 + cc], vp + (size_t)r * LK + cc, 16);
        }
        CP_COMMIT();
    };

    loadKV(0, KsA, VsA);

    // Q fragments straight from gmem (pre-scaled, permuted).
    uint32_t qa[4][4];
    {
        const __half* q0 = g_Q + (size_t)(qb + rq0) * DM + h * DH;
        const __half* q1 = g_Q + (size_t)(qb + rq0 + 8) * DM + h * DH;
#pragma unroll
        for (int ks = 0; ks < 4; ks++) {
            uint2 u0 = *(const uint2*)(q0 + ks * 16 + 4 * tig);
            uint2 u1 = *(const uint2*)(q1 + ks * 16 + 4 * tig);
            qa[ks][0] = u0.x; qa[ks][1] = u1.x; qa[ks][2] = u0.y; qa[ks][3] = u1.y;
        }
    }

    float m0 = -1e30f, m1 = -1e30f;
    float sc0s = 0.f, sc1s = 0.f;
    uint32_t pa[4][4];                 // P(kt-1) as fp16 A-fragments
    const uint32_t oneb[2] = {0x3C003C00u, 0x3C003C00u};
    float ol[4] = {0.f, 0.f, 0.f, 0.f};   // l via ones-column MMA
    float o[8][4];
#pragma unroll
    for (int i = 0; i < 8; i++)
#pragma unroll
        for (int e = 0; e < 4; e++) o[i][e] = 0.f;

    const int nktFull = 34 + 2 * qtp;
    const int nkt = nktFull < 65 ? nktFull : 65;
    for (int kt = 0; kt < nkt; kt++) {
        CP_WAIT(0);
        __syncthreads();

        __half* Ks = (kt & 1) ? KsB : KsA;

        // ---- S(kt) = Q @ K^T (exp2 domain) ----
        float s[8][4];
#pragma unroll
        for (int i = 0; i < 8; i++)
#pragma unroll
            for (int e = 0; e < 4; e++) s[i][e] = 0.f;

#pragma unroll
        for (int ks = 0; ks < 4; ks++) {
            const int off = ks * 16 + 4 * tig;
#pragma unroll
            for (int nt = 0; nt < 8; nt++) {
                uint2 kv = *(const uint2*)&Ks[(nt * 8 + gid) * 72 + off];
                uint32_t bb[2] = {kv.x, kv.y};
                mma16(s[nt], qa[ks], bb);
            }
        }

        // ---- deferred PV(kt-1): O = O*sc + P@V; l likewise via ones-MMA ----
        if (kt > 0) {
            __half* Vp = (kt & 1) ? VsA : VsB;
#pragma unroll
            for (int dt = 0; dt < 8; dt++) {
                o[dt][0] *= sc0s; o[dt][1] *= sc0s;
                o[dt][2] *= sc1s; o[dt][3] *= sc1s;
            }
            ol[0] *= sc0s; ol[1] *= sc0s; ol[2] *= sc1s; ol[3] *= sc1s;
#pragma unroll
            for (int g = 0; g < 4; g++) {
                const int off = g * 16 + 4 * tig;
#pragma unroll
                for (int dt = 0; dt < 8; dt++) {
                    uint2 vv = *(const uint2*)&Vp[(dt * 8 + gid) * 72 + off];
                    uint32_t bb[2] = {vv.x, vv.y};
                    mma16(o[dt], pa[g], bb);
                }
                mma16(ol, pa[g], oneb);
            }
        }

        __syncthreads();
        if (kt + 1 < nkt)
            loadKV(kt + 1, (kt & 1) ? KsA : KsB, (kt & 1) ? VsA : VsB);

        // ---- causal mask on last two k-tiles ----
        if (kt >= nkt - 2) {
            const int off = kt * 64 - QSTART - qb;
#pragma unroll
            for (int nt = 0; nt < 8; nt++) {
#pragma unroll
                for (int e = 0; e < 4; e++) {
                    int kc  = nt * 8 + 2 * tig + (e & 1);
                    int rit = warp * 16 + gid + ((e >> 1) << 3);
                    if (kc + off > rit) s[nt][e] = -1e30f;
                }
            }
        }

        // ---- online softmax(kt): rowmax + exp2 (no sum reduction) ----
        float rm0 = -1e30f, rm1 = -1e30f;
#pragma unroll
        for (int nt = 0; nt < 8; nt++) {
            rm0 = fmaxf(rm0, fmaxf(s[nt][0], s[nt][1]));
            rm1 = fmaxf(rm1, fmaxf(s[nt][2], s[nt][3]));
        }
        rm0 = fmaxf(rm0, __shfl_xor_sync(0xffffffffu, rm0, 1));
        rm0 = fmaxf(rm0, __shfl_xor_sync(0xffffffffu, rm0, 2));
        rm1 = fmaxf(rm1, __shfl_xor_sync(0xffffffffu, rm1, 1));
        rm1 = fmaxf(rm1, __shfl_xor_sync(0xffffffffu, rm1, 2));

        float mn0 = fmaxf(m0, rm0), mn1 = fmaxf(m1, rm1);
        sc0s = exp2f(m0 - mn0);
        sc1s = exp2f(m1 - mn1);
        m0 = mn0; m1 = mn1;

        // ---- pack P(kt) = exp2(s - m) into register A-fragments ----
#pragma unroll
        for (int g = 0; g < 4; g++) {
            pa[g][0] = h2u(exp2f(s[2 * g][0] - m0),     exp2f(s[2 * g][1] - m0));
            pa[g][1] = h2u(exp2f(s[2 * g][2] - m1),     exp2f(s[2 * g][3] - m1));
            pa[g][2] = h2u(exp2f(s[2 * g + 1][0] - m0), exp2f(s[2 * g + 1][1] - m0));
            pa[g][3] = h2u(exp2f(s[2 * g + 1][2] - m1), exp2f(s[2 * g + 1][3] - m1));
        }
    }

    // ---- final deferred PV(nkt-1) ----
    {
        __half* Vp = ((nkt - 1) & 1) ? VsB : VsA;
#pragma unroll
        for (int dt = 0; dt < 8; dt++) {
            o[dt][0] *= sc0s; o[dt][1] *= sc0s;
            o[dt][2] *= sc1s; o[dt][3] *= sc1s;
        }
        ol[0] *= sc0s; ol[1] *= sc0s; ol[2] *= sc1s; ol[3] *= sc1s;
#pragma unroll
        for (int g = 0; g < 4; g++) {
            const int off = g * 16 + 4 * tig;
#pragma unroll
            for (int dt = 0; dt < 8; dt++) {
                uint2 vv = *(const uint2*)&Vp[(dt * 8 + gid) * 72 + off];
                uint32_t bb[2] = {vv.x, vv.y};
                mma16(o[dt], pa[g], bb);
            }
            mma16(ol, pa[g], oneb);
        }
    }

    // Epilogue: g_AO fp16, k 16-block permuted (matches g_Wor).
    const float il0 = 1.f / ol[0], il1 = 1.f / ol[2];
    const int qr0 = qb + rq0, qr1 = qb + rq0 + 8;
#pragma unroll
    for (int dt = 0; dt < 8; dt++) {
        int col = h * DH + dt * 8 + 2 * tig;
        int db = col & ~15, p = perm16(col & 15);
        if (qr0 < LQ)
            *(uint32_t*)&g_AO[(size_t)qr0 * DM + db + p] =
                h2u(o[dt][0] * il0, o[dt][1] * il0);
        if (qr1 < LQ)
            *(uint32_t*)&g_AO[(size_t)qr1 * DM + db + p] =
                h2u(o[dt][2] * il1, o[dt][3] * il1);
    }
}

// ============================================================================
extern "C" void kernel_launch(void* const* d_in, const int* in_sizes, int n_in,
                              void* d_out, int out_size) {
    const float* x     = (const float*)d_in[0];
    const float* W_S   = (const float*)d_in[1];
    const float* W_NS  = (const float*)d_in[2];
    const float* W_out = (const float*)d_in[3];
    float* out = (float*)d_out;
    (void)in_sizes; (void)n_in; (void)out_size;

    const int gemm_smem = 36864 * 2;   // 73728 B
    const int attn_smem = 18432 * 2;   // 36864 B

    cudaFuncSetAttribute(fused_qkv,   cudaFuncAttributeMaxDynamicSharedMemorySize, gemm_smem);
    cudaFuncSetAttribute(gemm_out,    cudaFuncAttributeMaxDynamicSharedMemorySize, gemm_smem);
    cudaFuncSetAttribute(attn_kernel, cudaFuncAttributeMaxDynamicSharedMemorySize, attn_smem);

    // 0) prep: x/W_S/W_out -> fp16 permuted
    prep_x<<<512, 256>>>(x);
    prep_tr<<<dim3(3 * DM / 32, DM / 32), 256>>>(W_S, 0);
    prep_tr<<<dim3(DM / 32, DM / 32), 256>>>(W_out, 1);

    // 1+2) fused: live qkv GEMM tiles (640) + NS streaming (192)
    fused_qkv<<<832, 256, gemm_smem>>>(x, W_NS);

    // 2b) repack V (transpose + token 16-blk permute)
    repack_Vt<<<dim3(LK / 32, DM / 32), 256>>>();

    // 3) attention: 17 q-pair tiles x 16 heads, longest first
    attn_kernel<<<17 * NH, 256, attn_smem>>>();

    // 4) output projection, full K, direct stores
    gemm_out<<<dim3(1024 / 128, (LQ + 127) / 128), 256, gemm_smem>>>(out);
}